// round 2
// baseline (speedup 1.0000x reference)
#include <cuda_runtime.h>
#include <cuda_bf16.h>

// Problem constants
#define NB 4
#define NT 2048
#define ND 2048
#define NH 16
#define NHD 128
// B*H*T*HD == B*T*D == 16777216

// Scratch (device globals: allocation-free rule)
__device__ float g_Q[16777216];     // rotated Q, layout (b,h,t,d)  -- also the keys
__device__ float g_V[16777216];     // V, layout (b,h,t,d)
__device__ float g_attn[16777216];  // attention out, layout (b,t, h*HD) row-major

// ---------------------------------------------------------------------------
// SGEMM: C_tile = A(M,K) @ B(N,K)^T  (both row-major, K contiguous)
// 128x128 block tile, BK=8, 256 threads, 8x8 microtile, double-buffered smem.
// MODE 0: A=x, B=wq, epilogue applies double-angle RoPE, scatter -> g_Q (b,h,t,d)
// MODE 1: A=x, B=wv, scatter -> g_V (b,h,t,d)
// MODE 2: A=g_attn (internal), B=wo, store row-major -> C (d_out)
// ---------------------------------------------------------------------------
template<int MODE>
__global__ __launch_bounds__(256) void gemm128(
    const float* __restrict__ A,
    const float* __restrict__ Bw,
    float* __restrict__ C,
    const float* __restrict__ fc,
    const float* __restrict__ fs)
{
    constexpr int K = ND;
    __shared__ float As[2][8][128];
    __shared__ float Bs[2][8][128];

    const int tid = threadIdx.x;
    const int tx = tid & 15;        // 0..15 -> N microtiles
    const int ty = tid >> 4;        // 0..15 -> M microtiles
    const int bn = blockIdx.x;      // N tile (head index for MODE 0/1 since tile == HD)
    const int bm = blockIdx.y;      // M tile

    const int lr = tid >> 1;        // load row 0..127
    const int lc = (tid & 1) << 2;  // 0 or 4

    const float* Abase = (MODE == 2) ? g_attn : A;
    const float* Ap = Abase + (size_t)(bm * 128 + lr) * K + lc;
    const float* Bp = Bw    + (size_t)(bn * 128 + lr) * K + lc;

    float acc[8][8];
#pragma unroll
    for (int i = 0; i < 8; i++)
#pragma unroll
        for (int j = 0; j < 8; j++) acc[i][j] = 0.f;

    // Prologue: load first K-tile into buffer 0
    {
        float4 av = *(const float4*)(Ap);
        float4 bv = *(const float4*)(Bp);
        As[0][lc + 0][lr] = av.x; As[0][lc + 1][lr] = av.y;
        As[0][lc + 2][lr] = av.z; As[0][lc + 3][lr] = av.w;
        Bs[0][lc + 0][lr] = bv.x; Bs[0][lc + 1][lr] = bv.y;
        Bs[0][lc + 2][lr] = bv.z; Bs[0][lc + 3][lr] = bv.w;
    }
    __syncthreads();

    int buf = 0;
    for (int k0 = 8; k0 <= K; k0 += 8) {
        float4 av, bv;
        const bool more = (k0 < K);
        if (more) {
            av = *(const float4*)(Ap + k0);   // issue next tile's loads first
            bv = *(const float4*)(Bp + k0);
        }
#pragma unroll
        for (int k = 0; k < 8; k++) {
            float4 a0 = *(const float4*)&As[buf][k][ty * 8];
            float4 a1 = *(const float4*)&As[buf][k][ty * 8 + 4];
            float4 b0 = *(const float4*)&Bs[buf][k][tx * 8];
            float4 b1 = *(const float4*)&Bs[buf][k][tx * 8 + 4];
            float ar[8] = {a0.x, a0.y, a0.z, a0.w, a1.x, a1.y, a1.z, a1.w};
            float br[8] = {b0.x, b0.y, b0.z, b0.w, b1.x, b1.y, b1.z, b1.w};
#pragma unroll
            for (int i = 0; i < 8; i++)
#pragma unroll
                for (int j = 0; j < 8; j++)
                    acc[i][j] = fmaf(ar[i], br[j], acc[i][j]);
        }
        if (more) {
            int nb = buf ^ 1;
            As[nb][lc + 0][lr] = av.x; As[nb][lc + 1][lr] = av.y;
            As[nb][lc + 2][lr] = av.z; As[nb][lc + 3][lr] = av.w;
            Bs[nb][lc + 0][lr] = bv.x; Bs[nb][lc + 1][lr] = bv.y;
            Bs[nb][lc + 2][lr] = bv.z; Bs[nb][lc + 3][lr] = bv.w;
            __syncthreads();
            buf = nb;
        }
    }

    if (MODE == 0) {
        // RoPE (double angle, exactly as reference) then scatter to (b,h,t,d).
        const int h = bn;  // N tile == one head (128 cols)
#pragma unroll
        for (int i = 0; i < 8; i++) {
            int m = bm * 128 + ty * 8 + i;
            int b = m >> 11;          // / NT
            int t = m & (NT - 1);
            float ov[8];
#pragma unroll
            for (int jp = 0; jp < 4; jp++) {
                int p = tx * 4 + jp;              // pair index 0..63
                float c = fc[t * 64 + p];
                float s = fs[t * 64 + p];
                float c2 = c * c - s * s;
                float s2 = 2.f * c * s;
                float qr = acc[i][2 * jp];
                float qi = acc[i][2 * jp + 1];
                ov[2 * jp]     = qr * c2 - qi * s2;
                ov[2 * jp + 1] = qr * s2 + qi * c2;
            }
            size_t idx = (((size_t)b * NH + h) * NT + t) * NHD + tx * 8;
            *(float4*)&g_Q[idx]     = make_float4(ov[0], ov[1], ov[2], ov[3]);
            *(float4*)&g_Q[idx + 4] = make_float4(ov[4], ov[5], ov[6], ov[7]);
        }
    } else if (MODE == 1) {
        const int h = bn;
#pragma unroll
        for (int i = 0; i < 8; i++) {
            int m = bm * 128 + ty * 8 + i;
            int b = m >> 11;
            int t = m & (NT - 1);
            size_t idx = (((size_t)b * NH + h) * NT + t) * NHD + tx * 8;
            *(float4*)&g_V[idx]     = make_float4(acc[i][0], acc[i][1], acc[i][2], acc[i][3]);
            *(float4*)&g_V[idx + 4] = make_float4(acc[i][4], acc[i][5], acc[i][6], acc[i][7]);
        }
    } else {
#pragma unroll
        for (int i = 0; i < 8; i++) {
            int m = bm * 128 + ty * 8 + i;
            float* Cp = C + (size_t)m * ND + bn * 128 + tx * 8;
            *(float4*)Cp       = make_float4(acc[i][0], acc[i][1], acc[i][2], acc[i][3]);
            *(float4*)(Cp + 4) = make_float4(acc[i][4], acc[i][5], acc[i][6], acc[i][7]);
        }
    }
}

// ---------------------------------------------------------------------------
// Causal flash attention, fp32. K == Q (reference overwrites xk with rot(xq)).
// BQ = BKV = 64, HD = 128, 256 threads. Online softmax, scores*scale + causal.
// smem: Qst/Kst transposed [128][68] (d-major, padded), Vs [64][128], Ps [64][64].
// ---------------------------------------------------------------------------
#define FL_SMEM ((2 * 128 * 68 + 64 * 128 + 64 * 64) * (int)sizeof(float))

__global__ __launch_bounds__(256) void flash64()
{
    extern __shared__ float sm[];
    float* Qst = sm;                      // [128][68] transposed
    float* Kst = sm + 128 * 68;           // [128][68] transposed
    float* Vs  = sm + 2 * 128 * 68;       // [64][128]
    float* Ps  = sm + 2 * 128 * 68 + 64 * 128;  // [64][64]

    const int tid = threadIdx.x;
    const int tx = tid & 15;   // 4 key cols / 8 out cols
    const int ty = tid >> 4;   // 4 query rows
    const int bh = blockIdx.y;                       // 0..63 = b*16+h
    const int qb = (int)gridDim.x - 1 - (int)blockIdx.x;  // heavy blocks first

    const float* Qb = g_Q + (size_t)bh * NT * NHD;
    const float* Vb = g_V + (size_t)bh * NT * NHD;

    // Load Q block transposed: Qst[d][r]
    for (int i = tid; i < 64 * 32; i += 256) {
        int r = i >> 5, c4 = (i & 31) << 2;
        float4 v = *(const float4*)(Qb + (size_t)(qb * 64 + r) * NHD + c4);
        Qst[(c4 + 0) * 68 + r] = v.x;
        Qst[(c4 + 1) * 68 + r] = v.y;
        Qst[(c4 + 2) * 68 + r] = v.z;
        Qst[(c4 + 3) * 68 + r] = v.w;
    }

    float o[4][8];
#pragma unroll
    for (int i = 0; i < 4; i++)
#pragma unroll
        for (int c = 0; c < 8; c++) o[i][c] = 0.f;
    float mrow[4] = {-1e30f, -1e30f, -1e30f, -1e30f};
    float lrow[4] = {0.f, 0.f, 0.f, 0.f};
    const float scale = 0.08838834764831845f;  // 1/sqrt(128)

    for (int kb = 0; kb <= qb; kb++) {
        __syncthreads();  // prior-iteration readers of Kst/Vs/Ps are done
        // Load K chunk (== Q data) transposed, V chunk direct
        for (int i = tid; i < 64 * 32; i += 256) {
            int r = i >> 5, c4 = (i & 31) << 2;
            float4 kv = *(const float4*)(Qb + (size_t)(kb * 64 + r) * NHD + c4);
            Kst[(c4 + 0) * 68 + r] = kv.x;
            Kst[(c4 + 1) * 68 + r] = kv.y;
            Kst[(c4 + 2) * 68 + r] = kv.z;
            Kst[(c4 + 3) * 68 + r] = kv.w;
            float4 vv = *(const float4*)(Vb + (size_t)(kb * 64 + r) * NHD + c4);
            *(float4*)&Vs[r * 128 + c4] = vv;
        }
        __syncthreads();

        // S = Q K^T  (4x4 per thread)
        float s[4][4];
#pragma unroll
        for (int i = 0; i < 4; i++)
#pragma unroll
            for (int j = 0; j < 4; j++) s[i][j] = 0.f;

#pragma unroll 4
        for (int d = 0; d < 128; d++) {
            float4 qv = *(const float4*)&Qst[d * 68 + ty * 4];
            float4 kv = *(const float4*)&Kst[d * 68 + tx * 4];
            float qr[4] = {qv.x, qv.y, qv.z, qv.w};
            float kr[4] = {kv.x, kv.y, kv.z, kv.w};
#pragma unroll
            for (int i = 0; i < 4; i++)
#pragma unroll
                for (int j = 0; j < 4; j++)
                    s[i][j] = fmaf(qr[i], kr[j], s[i][j]);
        }

        // Online softmax (row groups of 16 lanes share a row set)
        const int q0 = qb * 64 + ty * 4;
        const int k0 = kb * 64 + tx * 4;
#pragma unroll
        for (int i = 0; i < 4; i++) {
            float sv[4];
            float mloc = -1e30f;
#pragma unroll
            for (int j = 0; j < 4; j++) {
                float v = s[i][j] * scale;
                if (k0 + j > q0 + i) v = -1e30f;  // mask: exp underflows to 0, same as ref's -1e9
                sv[j] = v;
                mloc = fmaxf(mloc, v);
            }
#pragma unroll
            for (int off = 8; off > 0; off >>= 1)
                mloc = fmaxf(mloc, __shfl_xor_sync(0xffffffffu, mloc, off));
            float mnew = fmaxf(mrow[i], mloc);
            float alpha = __expf(mrow[i] - mnew);
            float rs = 0.f;
#pragma unroll
            for (int j = 0; j < 4; j++) {
                float p = __expf(sv[j] - mnew);
                Ps[(ty * 4 + i) * 64 + tx * 4 + j] = p;
                rs += p;
            }
#pragma unroll
            for (int off = 8; off > 0; off >>= 1)
                rs += __shfl_xor_sync(0xffffffffu, rs, off);
            lrow[i] = lrow[i] * alpha + rs;
            mrow[i] = mnew;
#pragma unroll
            for (int c = 0; c < 8; c++) o[i][c] *= alpha;
        }
        __syncthreads();  // Ps visible to all

        // O += P @ V
#pragma unroll 2
        for (int j = 0; j < 64; j++) {
            float4 v0 = *(const float4*)&Vs[j * 128 + tx * 8];
            float4 v1 = *(const float4*)&Vs[j * 128 + tx * 8 + 4];
#pragma unroll
            for (int i = 0; i < 4; i++) {
                float p = Ps[(ty * 4 + i) * 64 + j];
                o[i][0] = fmaf(p, v0.x, o[i][0]);
                o[i][1] = fmaf(p, v0.y, o[i][1]);
                o[i][2] = fmaf(p, v0.z, o[i][2]);
                o[i][3] = fmaf(p, v0.w, o[i][3]);
                o[i][4] = fmaf(p, v1.x, o[i][4]);
                o[i][5] = fmaf(p, v1.y, o[i][5]);
                o[i][6] = fmaf(p, v1.z, o[i][6]);
                o[i][7] = fmaf(p, v1.w, o[i][7]);
            }
        }
    }

    // Normalize and store to (b, t, h*HD)
    const int b = bh >> 4;
    const int h = bh & 15;
#pragma unroll
    for (int i = 0; i < 4; i++) {
        int t = qb * 64 + ty * 4 + i;
        float inv = 1.0f / lrow[i];
        size_t idx = ((size_t)(b * NT + t)) * ND + h * NHD + tx * 8;
        *(float4*)&g_attn[idx] =
            make_float4(o[i][0] * inv, o[i][1] * inv, o[i][2] * inv, o[i][3] * inv);
        *(float4*)&g_attn[idx + 4] =
            make_float4(o[i][4] * inv, o[i][5] * inv, o[i][6] * inv, o[i][7] * inv);
    }
}

// ---------------------------------------------------------------------------
// Inputs (metadata order): 0:x 1:wq 2:wk(UNUSED: ref overwrites xk with rot(xq))
// 3:wv 4:wo 5:freqs_cos 6:freqs_sin 7:mask(causal, equiv) 8:cache_k 9:cache_v
// 10:start_pos(=0)
// ---------------------------------------------------------------------------
extern "C" void kernel_launch(void* const* d_in, const int* in_sizes, int n_in,
                              void* d_out, int out_size)
{
    const float* x  = (const float*)d_in[0];
    const float* wq = (const float*)d_in[1];
    const float* wv = (const float*)d_in[3];
    const float* wo = (const float*)d_in[4];
    const float* fc = (const float*)d_in[5];
    const float* fs = (const float*)d_in[6];
    float* out = (float*)d_out;

    cudaFuncSetAttribute((const void*)flash64,
                         cudaFuncAttributeMaxDynamicSharedMemorySize, FL_SMEM);

    dim3 blk(256);
    dim3 gGemm(ND / 128, (NB * NT) / 128);  // (16, 64)

    gemm128<0><<<gGemm, blk>>>(x, wq, nullptr, fc, fs);      // Q + RoPE
    gemm128<1><<<gGemm, blk>>>(x, wv, nullptr, nullptr, nullptr);  // V
    flash64<<<dim3(NT / 64, NB * NH), blk, FL_SMEM>>>();     // attention (K==Q)
    gemm128<2><<<gGemm, blk>>>(nullptr, wo, out, nullptr, nullptr);  // out proj
}

// round 3
// speedup vs baseline: 3.3448x; 3.3448x over previous
#include <cuda_runtime.h>
#include <cuda_bf16.h>

#define NB 4
#define NT 2048
#define ND 2048
#define NH 16
#define NHD 128

// Scratch (allocation-free rule)
__device__ float g_Q[16777216];     // rotated Q (b,h,t,d) — also the keys
__device__ float g_V[16777216];     // V (b,h,t,d)
__device__ float g_attn[16777216];  // attention out (b,t,h*HD)

// ---------------- MMA / ldmatrix helpers ----------------
__device__ __forceinline__ unsigned smaddr(const void* p) {
    return (unsigned)__cvta_generic_to_shared(p);
}
__device__ __forceinline__ void ldsm_x4(unsigned* r, unsigned a) {
    asm volatile("ldmatrix.sync.aligned.m8n8.x4.shared.b16 {%0,%1,%2,%3},[%4];"
        : "=r"(r[0]), "=r"(r[1]), "=r"(r[2]), "=r"(r[3]) : "r"(a));
}
__device__ __forceinline__ void ldsm_x2(unsigned* r, unsigned a) {
    asm volatile("ldmatrix.sync.aligned.m8n8.x2.shared.b16 {%0,%1},[%2];"
        : "=r"(r[0]), "=r"(r[1]) : "r"(a));
}
__device__ __forceinline__ void ldsm_x2t(unsigned* r, unsigned a) {
    asm volatile("ldmatrix.sync.aligned.m8n8.x2.trans.shared.b16 {%0,%1},[%2];"
        : "=r"(r[0]), "=r"(r[1]) : "r"(a));
}
__device__ __forceinline__ void mma_bf16(float* c, const unsigned* a, const unsigned* b) {
    asm volatile("mma.sync.aligned.m16n8k16.row.col.f32.bf16.bf16.f32 "
        "{%0,%1,%2,%3},{%4,%5,%6,%7},{%8,%9},{%0,%1,%2,%3};"
        : "+f"(c[0]), "+f"(c[1]), "+f"(c[2]), "+f"(c[3])
        : "r"(a[0]), "r"(a[1]), "r"(a[2]), "r"(a[3]), "r"(b[0]), "r"(b[1]));
}
__device__ __forceinline__ unsigned pack_bf16(__nv_bfloat16 a, __nv_bfloat16 b) {
    __nv_bfloat162 t; t.x = a; t.y = b;
    return *reinterpret_cast<unsigned*>(&t);
}
// split two fp32 into (hi-pair, lo-pair) bf16x2 registers
__device__ __forceinline__ void split2(float x, float y, unsigned& h, unsigned& l) {
    __nv_bfloat16 hx = __float2bfloat16(x);
    __nv_bfloat16 hy = __float2bfloat16(y);
    float rx = x - __bfloat162float(hx);
    float ry = y - __bfloat162float(hy);
    h = pack_bf16(hx, hy);
    l = pack_bf16(__float2bfloat16(rx), __float2bfloat16(ry));
}

// ===========================================================================
// Split-bf16 tensor-core GEMM: C = A(M,K) @ W(N,K)^T, 128x128 tile, BK=16.
// 256 threads = 8 warps (2x4), warp tile 64x32. Double-buffered hi/lo smem.
// MODE 0: A=x, W=wq, RoPE epilogue -> g_Q(b,h,t,d)
// MODE 1: A=x, W=wv            -> g_V(b,h,t,d)
// MODE 2: A=g_attn, W=wo       -> C row-major (d_out)
// ===========================================================================
#define GSTR 24                 // bf16 row stride (conflict-free ldmatrix)
#define G_TILE (128 * GSTR)     // elems per (buf,array)
#define G_SMEM_BYTES (8 * G_TILE * 2)   // 49152 B

template<int MODE>
__global__ __launch_bounds__(256) void tgemm(
    const float* __restrict__ A, const float* __restrict__ Bw,
    float* __restrict__ C, const float* __restrict__ fc, const float* __restrict__ fs)
{
    constexpr int K = ND;
    constexpr int NSTG = K / 16;  // 128
    extern __shared__ __nv_bfloat16 sm[];
    __nv_bfloat16* sAh = sm;
    __nv_bfloat16* sAl = sm + 2 * G_TILE;
    __nv_bfloat16* sBh = sm + 4 * G_TILE;
    __nv_bfloat16* sBl = sm + 6 * G_TILE;
    const unsigned bAh = smaddr(sAh), bAl = smaddr(sAl);
    const unsigned bBh = smaddr(sBh), bBl = smaddr(sBl);

    const int tid = threadIdx.x;
    const int warp = tid >> 5, lane = tid & 31;
    const int wm = warp >> 2, wn = warp & 3;
    const int bn = blockIdx.x, bm = blockIdx.y;

    // global loaders: thread covers row=tid>>1, cols cb..cb+7
    const int lrow = tid >> 1, cb = (tid & 1) * 8;
    const float* Abase = (MODE == 2) ? g_attn : A;
    const float* Ap = Abase + (size_t)(bm * 128 + lrow) * K + cb;
    const float* Bp = Bw    + (size_t)(bn * 128 + lrow) * K + cb;
    const int stoff = lrow * GSTR + cb;  // elem offset within tile

    // ldmatrix lane geometry
    const int sel = lane >> 3;
    const int rA = wm * 64 + (sel & 1) * 8 + (lane & 7);
    const int cA = (sel >> 1) * 8;
    const int lane2 = lane & 15;
    const int rB = wn * 32 + (lane2 & 7);
    const int cBld = (lane2 >> 3) * 8;

    float acc[4][4][4];
#pragma unroll
    for (int i = 0; i < 4; i++)
#pragma unroll
        for (int j = 0; j < 4; j++)
#pragma unroll
            for (int k = 0; k < 4; k++) acc[i][j][k] = 0.f;

    // prologue: stage 0 -> buf 0
    {
        float4 a0 = *(const float4*)(Ap);
        float4 a1 = *(const float4*)(Ap + 4);
        float4 b0 = *(const float4*)(Bp);
        float4 b1 = *(const float4*)(Bp + 4);
        unsigned h, l;
        split2(a0.x, a0.y, h, l); *(unsigned*)&sAh[stoff]     = h; *(unsigned*)&sAl[stoff]     = l;
        split2(a0.z, a0.w, h, l); *(unsigned*)&sAh[stoff + 2] = h; *(unsigned*)&sAl[stoff + 2] = l;
        split2(a1.x, a1.y, h, l); *(unsigned*)&sAh[stoff + 4] = h; *(unsigned*)&sAl[stoff + 4] = l;
        split2(a1.z, a1.w, h, l); *(unsigned*)&sAh[stoff + 6] = h; *(unsigned*)&sAl[stoff + 6] = l;
        split2(b0.x, b0.y, h, l); *(unsigned*)&sBh[stoff]     = h; *(unsigned*)&sBl[stoff]     = l;
        split2(b0.z, b0.w, h, l); *(unsigned*)&sBh[stoff + 2] = h; *(unsigned*)&sBl[stoff + 2] = l;
        split2(b1.x, b1.y, h, l); *(unsigned*)&sBh[stoff + 4] = h; *(unsigned*)&sBl[stoff + 4] = l;
        split2(b1.z, b1.w, h, l); *(unsigned*)&sBh[stoff + 6] = h; *(unsigned*)&sBl[stoff + 6] = l;
    }
    __syncthreads();

    for (int s = 0; s < NSTG; s++) {
        const int buf = s & 1;
        float4 a0n, a1n, b0n, b1n;
        const bool more = (s + 1 < NSTG);
        if (more) {
            a0n = *(const float4*)(Ap + (s + 1) * 16);
            a1n = *(const float4*)(Ap + (s + 1) * 16 + 4);
            b0n = *(const float4*)(Bp + (s + 1) * 16);
            b1n = *(const float4*)(Bp + (s + 1) * 16 + 4);
        }
        // compute on buf
        {
            const unsigned bufB = (unsigned)(buf * G_TILE * 2);
            unsigned bh[4][2], bl[4][2];
#pragma unroll
            for (int ni = 0; ni < 4; ni++) {
                unsigned off = bufB + ((rB + ni * 8) * GSTR + cBld) * 2;
                ldsm_x2(bh[ni], bBh + off);
                ldsm_x2(bl[ni], bBl + off);
            }
#pragma unroll
            for (int mi = 0; mi < 4; mi++) {
                unsigned off = bufB + ((rA + mi * 16) * GSTR + cA) * 2;
                unsigned ah[4], al[4];
                ldsm_x4(ah, bAh + off);
                ldsm_x4(al, bAl + off);
#pragma unroll
                for (int ni = 0; ni < 4; ni++) {
                    mma_bf16(acc[mi][ni], ah, bh[ni]);
                    mma_bf16(acc[mi][ni], ah, bl[ni]);
                    mma_bf16(acc[mi][ni], al, bh[ni]);
                }
            }
        }
        if (more) {
            const int so = (buf ^ 1) * G_TILE + stoff;
            unsigned h, l;
            split2(a0n.x, a0n.y, h, l); *(unsigned*)&sAh[so]     = h; *(unsigned*)&sAl[so]     = l;
            split2(a0n.z, a0n.w, h, l); *(unsigned*)&sAh[so + 2] = h; *(unsigned*)&sAl[so + 2] = l;
            split2(a1n.x, a1n.y, h, l); *(unsigned*)&sAh[so + 4] = h; *(unsigned*)&sAl[so + 4] = l;
            split2(a1n.z, a1n.w, h, l); *(unsigned*)&sAh[so + 6] = h; *(unsigned*)&sAl[so + 6] = l;
            split2(b0n.x, b0n.y, h, l); *(unsigned*)&sBh[so]     = h; *(unsigned*)&sBl[so]     = l;
            split2(b0n.z, b0n.w, h, l); *(unsigned*)&sBh[so + 2] = h; *(unsigned*)&sBl[so + 2] = l;
            split2(b1n.x, b1n.y, h, l); *(unsigned*)&sBh[so + 4] = h; *(unsigned*)&sBl[so + 4] = l;
            split2(b1n.z, b1n.w, h, l); *(unsigned*)&sBh[so + 6] = h; *(unsigned*)&sBl[so + 6] = l;
            __syncthreads();
        }
    }

    // -------- epilogue --------
    const int colBase = wn * 32 + (lane & 3) * 2;  // within-tile even col
#pragma unroll
    for (int mi = 0; mi < 4; mi++) {
        const int m0 = bm * 128 + wm * 64 + mi * 16 + (lane >> 2);
#pragma unroll
        for (int rr = 0; rr < 2; rr++) {
            const int m = m0 + rr * 8;
            const float c0 = acc[mi][0][rr * 2], c1v = acc[mi][0][rr * 2 + 1];
            (void)c0; (void)c1v;
            if (MODE == 0) {
                const int b = m >> 11, t = m & (NT - 1);
                const int h = bn;
#pragma unroll
                for (int ni = 0; ni < 4; ni++) {
                    const int hd = colBase + ni * 8;     // even
                    const int p = hd >> 1;
                    float c = fc[t * 64 + p], s = fs[t * 64 + p];
                    float c2 = c * c - s * s, s2 = 2.f * c * s;
                    float qr = acc[mi][ni][rr * 2], qi = acc[mi][ni][rr * 2 + 1];
                    float2 o = make_float2(qr * c2 - qi * s2, qr * s2 + qi * c2);
                    size_t idx = (((size_t)b * NH + h) * NT + t) * NHD + hd;
                    *(float2*)&g_Q[idx] = o;
                }
            } else if (MODE == 1) {
                const int b = m >> 11, t = m & (NT - 1);
                const int h = bn;
#pragma unroll
                for (int ni = 0; ni < 4; ni++) {
                    const int hd = colBase + ni * 8;
                    size_t idx = (((size_t)b * NH + h) * NT + t) * NHD + hd;
                    *(float2*)&g_V[idx] = make_float2(acc[mi][ni][rr * 2], acc[mi][ni][rr * 2 + 1]);
                }
            } else {
#pragma unroll
                for (int ni = 0; ni < 4; ni++) {
                    const int n = bn * 128 + colBase + ni * 8;
                    *(float2*)&C[(size_t)m * ND + n] =
                        make_float2(acc[mi][ni][rr * 2], acc[mi][ni][rr * 2 + 1]);
                }
            }
        }
    }
}

// ===========================================================================
// Tensor-core causal flash attention, split-bf16. K == Q (reference aliasing).
// BQ=128, BKV=64, 256 threads = 8 warps, each warp owns 16 q rows.
// Q natural [q][d] (A-frag), K natural [kv][d] (B-frag), V natural with
// ldmatrix.trans (B-frag for PV). P built in registers from S accumulators.
// ===========================================================================
#define FSTR 136
#define F_Q  (128 * FSTR)
#define F_K  (64 * FSTR)
#define FL_SMEM_TC ((2 * F_Q + 4 * F_K) * 2)   // bytes = 139264

__global__ __launch_bounds__(256) void flash_tc()
{
    extern __shared__ __nv_bfloat16 fsm[];
    __nv_bfloat16* Qh = fsm;
    __nv_bfloat16* Ql = fsm + F_Q;
    __nv_bfloat16* Kh = fsm + 2 * F_Q;
    __nv_bfloat16* Kl = fsm + 2 * F_Q + F_K;
    __nv_bfloat16* Vh = fsm + 2 * F_Q + 2 * F_K;
    __nv_bfloat16* Vl = fsm + 2 * F_Q + 3 * F_K;
    const unsigned aQh = smaddr(Qh), aQl = smaddr(Ql);
    const unsigned aKh = smaddr(Kh), aKl = smaddr(Kl);
    const unsigned aVh = smaddr(Vh), aVl = smaddr(Vl);

    const int tid = threadIdx.x;
    const int warp = tid >> 5, lane = tid & 31;
    const int bh = blockIdx.y;
    const int qb = (int)gridDim.x - 1 - (int)blockIdx.x;   // heavy first
    const int b = bh >> 4, h = bh & 15;

    const float* Qg = g_Q + (size_t)bh * NT * NHD;
    const float* Vg = g_V + (size_t)bh * NT * NHD;

    // load Q block (128x128) -> hi/lo smem
#pragma unroll
    for (int i = 0; i < 16; i++) {
        int e = tid + i * 256;
        int row = e >> 5, c4 = (e & 31) << 2;
        float4 v = *(const float4*)(Qg + (size_t)(qb * 128 + row) * NHD + c4);
        int off = row * FSTR + c4;
        unsigned hh, ll;
        split2(v.x, v.y, hh, ll); *(unsigned*)&Qh[off]     = hh; *(unsigned*)&Ql[off]     = ll;
        split2(v.z, v.w, hh, ll); *(unsigned*)&Qh[off + 2] = hh; *(unsigned*)&Ql[off + 2] = ll;
    }

    float oacc[16][4];
#pragma unroll
    for (int i = 0; i < 16; i++)
#pragma unroll
        for (int k = 0; k < 4; k++) oacc[i][k] = 0.f;
    float m0 = -1e30f, m1 = -1e30f, l0s = 0.f, l1s = 0.f;
    const float scale = 0.08838834764831845f;

    const int sel = lane >> 3;
    const int lane2 = lane & 15;
    const int qRow = warp * 16 + (sel & 1) * 8 + (lane & 7);
    const int qCol = (sel >> 1) * 8;
    const int r0g = qb * 128 + warp * 16 + (lane >> 2);
    const int r1g = r0g + 8;

    const int kbmax = 2 * qb + 1;
    for (int kb = 0; kb <= kbmax; kb++) {
        __syncthreads();  // Q ready (1st) / prior mma reads of K,V done
#pragma unroll
        for (int i = 0; i < 8; i++) {
            int e = tid + i * 256;
            int row = e >> 5, c4 = (e & 31) << 2;
            int off = row * FSTR + c4;
            float4 kv = *(const float4*)(Qg + (size_t)(kb * 64 + row) * NHD + c4);
            unsigned hh, ll;
            split2(kv.x, kv.y, hh, ll); *(unsigned*)&Kh[off]     = hh; *(unsigned*)&Kl[off]     = ll;
            split2(kv.z, kv.w, hh, ll); *(unsigned*)&Kh[off + 2] = hh; *(unsigned*)&Kl[off + 2] = ll;
            float4 vv = *(const float4*)(Vg + (size_t)(kb * 64 + row) * NHD + c4);
            split2(vv.x, vv.y, hh, ll); *(unsigned*)&Vh[off]     = hh; *(unsigned*)&Vl[off]     = ll;
            split2(vv.z, vv.w, hh, ll); *(unsigned*)&Vh[off + 2] = hh; *(unsigned*)&Vl[off + 2] = ll;
        }
        __syncthreads();

        // ---- S = Q K^T ----
        float sacc[8][4];
#pragma unroll
        for (int i = 0; i < 8; i++)
#pragma unroll
            for (int k = 0; k < 4; k++) sacc[i][k] = 0.f;

#pragma unroll
        for (int kd = 0; kd < 8; kd++) {
            unsigned offQ = (unsigned)((qRow * FSTR + kd * 16 + qCol) * 2);
            unsigned qfh[4], qfl[4];
            ldsm_x4(qfh, aQh + offQ);
            ldsm_x4(qfl, aQl + offQ);
#pragma unroll
            for (int ni = 0; ni < 8; ni++) {
                unsigned offK = (unsigned)(((ni * 8 + (lane2 & 7)) * FSTR + kd * 16 + (lane2 >> 3) * 8) * 2);
                unsigned kfh[2], kfl[2];
                ldsm_x2(kfh, aKh + offK);
                ldsm_x2(kfl, aKl + offK);
                mma_bf16(sacc[ni], qfh, kfh);
                mma_bf16(sacc[ni], qfh, kfl);
                mma_bf16(sacc[ni], qfl, kfh);
            }
        }

        // ---- mask + online softmax ----
        float vmax0 = m0, vmax1 = m1;
#pragma unroll
        for (int ni = 0; ni < 8; ni++) {
            int kg = kb * 64 + ni * 8 + (lane & 3) * 2;
            float v0 = sacc[ni][0] * scale; if (kg     > r0g) v0 = -1e30f;
            float v1 = sacc[ni][1] * scale; if (kg + 1 > r0g) v1 = -1e30f;
            float v2 = sacc[ni][2] * scale; if (kg     > r1g) v2 = -1e30f;
            float v3 = sacc[ni][3] * scale; if (kg + 1 > r1g) v3 = -1e30f;
            sacc[ni][0] = v0; sacc[ni][1] = v1; sacc[ni][2] = v2; sacc[ni][3] = v3;
            vmax0 = fmaxf(vmax0, fmaxf(v0, v1));
            vmax1 = fmaxf(vmax1, fmaxf(v2, v3));
        }
        vmax0 = fmaxf(vmax0, __shfl_xor_sync(0xffffffffu, vmax0, 1));
        vmax0 = fmaxf(vmax0, __shfl_xor_sync(0xffffffffu, vmax0, 2));
        vmax1 = fmaxf(vmax1, __shfl_xor_sync(0xffffffffu, vmax1, 1));
        vmax1 = fmaxf(vmax1, __shfl_xor_sync(0xffffffffu, vmax1, 2));
        const float alpha0 = __expf(m0 - vmax0);
        const float alpha1 = __expf(m1 - vmax1);
        m0 = vmax0; m1 = vmax1;
        float rs0 = 0.f, rs1 = 0.f;
#pragma unroll
        for (int ni = 0; ni < 8; ni++) {
            float p0 = __expf(sacc[ni][0] - m0);
            float p1 = __expf(sacc[ni][1] - m0);
            float p2 = __expf(sacc[ni][2] - m1);
            float p3 = __expf(sacc[ni][3] - m1);
            sacc[ni][0] = p0; sacc[ni][1] = p1; sacc[ni][2] = p2; sacc[ni][3] = p3;
            rs0 += p0 + p1; rs1 += p2 + p3;
        }
        rs0 += __shfl_xor_sync(0xffffffffu, rs0, 1);
        rs0 += __shfl_xor_sync(0xffffffffu, rs0, 2);
        rs1 += __shfl_xor_sync(0xffffffffu, rs1, 1);
        rs1 += __shfl_xor_sync(0xffffffffu, rs1, 2);
        l0s = l0s * alpha0 + rs0;
        l1s = l1s * alpha1 + rs1;
#pragma unroll
        for (int ni = 0; ni < 16; ni++) {
            oacc[ni][0] *= alpha0; oacc[ni][1] *= alpha0;
            oacc[ni][2] *= alpha1; oacc[ni][3] *= alpha1;
        }

        // ---- O += P V ----
#pragma unroll
        for (int j = 0; j < 4; j++) {
            unsigned ah[4], al[4];
            {
                unsigned h0, l0, h1, l1, h2, l2, h3, l3;
                split2(sacc[2 * j][0], sacc[2 * j][1], h0, l0);
                split2(sacc[2 * j][2], sacc[2 * j][3], h1, l1);
                split2(sacc[2 * j + 1][0], sacc[2 * j + 1][1], h2, l2);
                split2(sacc[2 * j + 1][2], sacc[2 * j + 1][3], h3, l3);
                ah[0] = h0; ah[1] = h1; ah[2] = h2; ah[3] = h3;
                al[0] = l0; al[1] = l1; al[2] = l2; al[3] = l3;
            }
#pragma unroll
            for (int ni = 0; ni < 16; ni++) {
                unsigned offV = (unsigned)(((j * 16 + (lane2 >> 3) * 8 + (lane2 & 7)) * FSTR + ni * 8) * 2);
                unsigned vfh[2], vfl[2];
                ldsm_x2t(vfh, aVh + offV);
                ldsm_x2t(vfl, aVl + offV);
                mma_bf16(oacc[ni], ah, vfh);
                mma_bf16(oacc[ni], ah, vfl);
                mma_bf16(oacc[ni], al, vfh);
            }
        }
    }

    // ---- normalize + store (b, t, h*HD) ----
    const float inv0 = 1.0f / l0s;
    const float inv1 = 1.0f / l1s;
    const int t0 = qb * 128 + warp * 16 + (lane >> 2);
    const int t1 = t0 + 8;
#pragma unroll
    for (int ni = 0; ni < 16; ni++) {
        const int d = ni * 8 + (lane & 3) * 2;
        size_t i0 = ((size_t)(b * NT + t0)) * ND + h * NHD + d;
        size_t i1 = ((size_t)(b * NT + t1)) * ND + h * NHD + d;
        *(float2*)&g_attn[i0] = make_float2(oacc[ni][0] * inv0, oacc[ni][1] * inv0);
        *(float2*)&g_attn[i1] = make_float2(oacc[ni][2] * inv1, oacc[ni][3] * inv1);
    }
}

// ---------------------------------------------------------------------------
// Inputs: 0:x 1:wq 2:wk(dead — ref overwrites xk with rot(xq)) 3:wv 4:wo
// 5:freqs_cos 6:freqs_sin 7:mask(causal-equiv) 8:cache_k 9:cache_v 10:start_pos
// ---------------------------------------------------------------------------
extern "C" void kernel_launch(void* const* d_in, const int* in_sizes, int n_in,
                              void* d_out, int out_size)
{
    const float* x  = (const float*)d_in[0];
    const float* wq = (const float*)d_in[1];
    const float* wv = (const float*)d_in[3];
    const float* wo = (const float*)d_in[4];
    const float* fc = (const float*)d_in[5];
    const float* fs = (const float*)d_in[6];
    float* out = (float*)d_out;

    cudaFuncSetAttribute((const void*)tgemm<0>,
                         cudaFuncAttributeMaxDynamicSharedMemorySize, G_SMEM_BYTES);
    cudaFuncSetAttribute((const void*)tgemm<1>,
                         cudaFuncAttributeMaxDynamicSharedMemorySize, G_SMEM_BYTES);
    cudaFuncSetAttribute((const void*)tgemm<2>,
                         cudaFuncAttributeMaxDynamicSharedMemorySize, G_SMEM_BYTES);
    cudaFuncSetAttribute((const void*)flash_tc,
                         cudaFuncAttributeMaxDynamicSharedMemorySize, FL_SMEM_TC);

    dim3 blk(256);
    dim3 gGemm(ND / 128, (NB * NT) / 128);  // (16, 64)

    tgemm<0><<<gGemm, blk, G_SMEM_BYTES>>>(x, wq, nullptr, fc, fs);
    tgemm<1><<<gGemm, blk, G_SMEM_BYTES>>>(x, wv, nullptr, nullptr, nullptr);
    flash_tc<<<dim3(NT / 128, NB * NH), blk, FL_SMEM_TC>>>();
    tgemm<2><<<gGemm, blk, G_SMEM_BYTES>>>(nullptr, wo, out, nullptr, nullptr);
}